// round 1
// baseline (speedup 1.0000x reference)
#include <cuda_runtime.h>
#include <cstdint>

#define LRELU_ALPHA 0.2f
#define NROWS 200000
#define IN_F  256
#define OUT_F 128

// rows per block / threading for the fused kernel
#define RPB      64
#define THREADS  256
#define MSTRIDE  260   // mix row stride in floats (pad: 260 % 32 = 4 -> conflict-free, 16B aligned)
#define SMEM_FLOATS (2 * IN_F + RPB * MSTRIDE)
#define SMEM_BYTES  (SMEM_FLOATS * 4)

// scratch for u_top (0..255) and u_bot (256..511)
__device__ float g_u[2 * IN_F];

// ---------------------------------------------------------------------------
// packed fp32x2 helpers (Blackwell FFMA2 via PTX; 2x FMA throughput vs FFMA)
// ---------------------------------------------------------------------------
__device__ __forceinline__ unsigned long long pack2(float lo, float hi) {
    unsigned long long r;
    asm("mov.b64 %0, {%1, %2};" : "=l"(r) : "f"(lo), "f"(hi));
    return r;
}
__device__ __forceinline__ void ffma2(unsigned long long& d,
                                      unsigned long long a,
                                      unsigned long long b) {
    asm("fma.rn.f32x2 %0, %1, %2, %0;" : "+l"(d) : "l"(a), "l"(b));
}
__device__ __forceinline__ void unpack2(unsigned long long v, float& lo, float& hi) {
    asm("mov.b64 {%0, %1}, %2;" : "=f"(lo), "=f"(hi) : "l"(v));
}

// ---------------------------------------------------------------------------
// Kernel 1: u_top[i] = sum_j W[i][j] * s[j],  u_bot[i] = sum_j W[i][j] * s[128+j]
// ---------------------------------------------------------------------------
__global__ void compute_u_kernel(const float* __restrict__ W,
                                 const float* __restrict__ s) {
    int i = threadIdx.x;  // 0..255
    const float* wrow = W + i * OUT_F;
    float ut = 0.f, ub = 0.f;
#pragma unroll 8
    for (int j = 0; j < OUT_F; ++j) {
        float w = wrow[j];
        ut = fmaf(w, s[j], ut);
        ub = fmaf(w, s[OUT_F + j], ub);
    }
    g_u[i] = ut;
    g_u[IN_F + i] = ub;
}

// ---------------------------------------------------------------------------
// Kernel 2: fused logits -> softmax -> mix -> (mix @ W)
// One block = 64 rows. Phase 1: per-row dots + softmax + mixed row into smem.
// Phase 2: 64x128x256 register-tiled GEMM with FFMA2.
// ---------------------------------------------------------------------------
__global__ __launch_bounds__(THREADS, 2)
void fused_attention_kernel(const float* __restrict__ T,
                            const float* __restrict__ O1,
                            const float* __restrict__ O2,
                            const float* __restrict__ W,
                            float* __restrict__ out) {
    extern __shared__ float sm[];
    float* s_u   = sm;            // 512 floats: u_top | u_bot
    float* s_mix = sm + 2 * IN_F; // RPB x MSTRIDE

    const int tid  = threadIdx.x;
    const int lane = tid & 31;
    const int warp = tid >> 5;
    const int row0 = blockIdx.x * RPB;

    // cooperative load of u vectors
    for (int i = tid; i < 2 * IN_F; i += THREADS) s_u[i] = g_u[i];
    __syncthreads();

    // ---------------- Phase 1: attention weights + mixed rows ----------------
    {
        // this lane owns elements [lane*8, lane*8+8)
        const float4* up = reinterpret_cast<const float4*>(s_u) + lane * 2;
        const float4 ut0 = up[0], ut1 = up[1];
        const float4* bp = reinterpret_cast<const float4*>(s_u + IN_F) + lane * 2;
        const float4 ub0 = bp[0], ub1 = bp[1];

        // 8 rows per warp
#pragma unroll
        for (int rr = 0; rr < RPB / 8; ++rr) {
            const int r = warp * (RPB / 8) + rr;      // 0..63
            const long long g = (long long)(row0 + r);
            const float4* tp = reinterpret_cast<const float4*>(T  + g * IN_F) + lane * 2;
            const float4* p1 = reinterpret_cast<const float4*>(O1 + g * IN_F) + lane * 2;
            const float4* p2 = reinterpret_cast<const float4*>(O2 + g * IN_F) + lane * 2;
            float4 t0 = tp[0], t1 = tp[1];
            float4 a0v = p1[0], a1v = p1[1];
            float4 b0v = p2[0], b1v = p2[1];

            float dtt = 0.f, dtb = 0.f, d1 = 0.f, d2 = 0.f;
            // t . u_top
            dtt = fmaf(t0.x, ut0.x, dtt); dtt = fmaf(t0.y, ut0.y, dtt);
            dtt = fmaf(t0.z, ut0.z, dtt); dtt = fmaf(t0.w, ut0.w, dtt);
            dtt = fmaf(t1.x, ut1.x, dtt); dtt = fmaf(t1.y, ut1.y, dtt);
            dtt = fmaf(t1.z, ut1.z, dtt); dtt = fmaf(t1.w, ut1.w, dtt);
            // t . u_bot
            dtb = fmaf(t0.x, ub0.x, dtb); dtb = fmaf(t0.y, ub0.y, dtb);
            dtb = fmaf(t0.z, ub0.z, dtb); dtb = fmaf(t0.w, ub0.w, dtb);
            dtb = fmaf(t1.x, ub1.x, dtb); dtb = fmaf(t1.y, ub1.y, dtb);
            dtb = fmaf(t1.z, ub1.z, dtb); dtb = fmaf(t1.w, ub1.w, dtb);
            // o1 . u_bot
            d1 = fmaf(a0v.x, ub0.x, d1); d1 = fmaf(a0v.y, ub0.y, d1);
            d1 = fmaf(a0v.z, ub0.z, d1); d1 = fmaf(a0v.w, ub0.w, d1);
            d1 = fmaf(a1v.x, ub1.x, d1); d1 = fmaf(a1v.y, ub1.y, d1);
            d1 = fmaf(a1v.z, ub1.z, d1); d1 = fmaf(a1v.w, ub1.w, d1);
            // o2 . u_bot
            d2 = fmaf(b0v.x, ub0.x, d2); d2 = fmaf(b0v.y, ub0.y, d2);
            d2 = fmaf(b0v.z, ub0.z, d2); d2 = fmaf(b0v.w, ub0.w, d2);
            d2 = fmaf(b1v.x, ub1.x, d2); d2 = fmaf(b1v.y, ub1.y, d2);
            d2 = fmaf(b1v.z, ub1.z, d2); d2 = fmaf(b1v.w, ub1.w, d2);

            // warp reduction of the 4 dots
#pragma unroll
            for (int off = 16; off; off >>= 1) {
                dtt += __shfl_xor_sync(0xffffffffu, dtt, off);
                dtb += __shfl_xor_sync(0xffffffffu, dtb, off);
                d1  += __shfl_xor_sync(0xffffffffu, d1,  off);
                d2  += __shfl_xor_sync(0xffffffffu, d2,  off);
            }

            float e0 = dtt + dtb, e1 = dtt + d1, e2 = dtt + d2;
            e0 = e0 > 0.f ? e0 : LRELU_ALPHA * e0;
            e1 = e1 > 0.f ? e1 : LRELU_ALPHA * e1;
            e2 = e2 > 0.f ? e2 : LRELU_ALPHA * e2;
            float m = fmaxf(e0, fmaxf(e1, e2));
            float w0 = expf(e0 - m), w1 = expf(e1 - m), w2 = expf(e2 - m);
            float inv = 1.f / (w0 + w1 + w2);
            w0 *= inv; w1 *= inv; w2 *= inv;

            // mixed row -> smem
            float4 m0, m1;
            m0.x = fmaf(w0, t0.x, fmaf(w1, a0v.x, w2 * b0v.x));
            m0.y = fmaf(w0, t0.y, fmaf(w1, a0v.y, w2 * b0v.y));
            m0.z = fmaf(w0, t0.z, fmaf(w1, a0v.z, w2 * b0v.z));
            m0.w = fmaf(w0, t0.w, fmaf(w1, a0v.w, w2 * b0v.w));
            m1.x = fmaf(w0, t1.x, fmaf(w1, a1v.x, w2 * b1v.x));
            m1.y = fmaf(w0, t1.y, fmaf(w1, a1v.y, w2 * b1v.y));
            m1.z = fmaf(w0, t1.z, fmaf(w1, a1v.z, w2 * b1v.z));
            m1.w = fmaf(w0, t1.w, fmaf(w1, a1v.w, w2 * b1v.w));
            float4* dst = reinterpret_cast<float4*>(&s_mix[r * MSTRIDE + lane * 8]);
            dst[0] = m0;
            dst[1] = m1;
        }
    }
    __syncthreads();

    // ---------------- Phase 2: out[64 x 128] = mix[64 x 256] @ W[256 x 128] --
    {
        const int rg = tid >> 4;   // 0..15 -> rows rg*4 .. rg*4+3
        const int cg = tid & 15;   // 0..15 -> cols cg*8 .. cg*8+7

        unsigned long long acc[4][4];
#pragma unroll
        for (int j = 0; j < 4; ++j)
#pragma unroll
            for (int c = 0; c < 4; ++c) acc[j][c] = 0ULL;

        const float* wcol = W + cg * 8;

        for (int k = 0; k < IN_F; k += 4) {
            float4 mv[4];
#pragma unroll
            for (int j = 0; j < 4; ++j)
                mv[j] = *reinterpret_cast<const float4*>(
                    &s_mix[(rg * 4 + j) * MSTRIDE + k]);
#pragma unroll
            for (int kk = 0; kk < 4; ++kk) {
                const float4* wp =
                    reinterpret_cast<const float4*>(wcol + (k + kk) * OUT_F);
                float4 w0 = wp[0], w1 = wp[1];
                unsigned long long wv0 = pack2(w0.x, w0.y);
                unsigned long long wv1 = pack2(w0.z, w0.w);
                unsigned long long wv2 = pack2(w1.x, w1.y);
                unsigned long long wv3 = pack2(w1.z, w1.w);
#pragma unroll
                for (int j = 0; j < 4; ++j) {
                    float mval = (kk == 0) ? mv[j].x
                               : (kk == 1) ? mv[j].y
                               : (kk == 2) ? mv[j].z
                                           : mv[j].w;
                    unsigned long long mp = pack2(mval, mval);
                    ffma2(acc[j][0], mp, wv0);
                    ffma2(acc[j][1], mp, wv1);
                    ffma2(acc[j][2], mp, wv2);
                    ffma2(acc[j][3], mp, wv3);
                }
            }
        }

        const long long orow0 = (long long)(row0 + rg * 4);
#pragma unroll
        for (int j = 0; j < 4; ++j) {
            float4 r0, r1;
            unpack2(acc[j][0], r0.x, r0.y);
            unpack2(acc[j][1], r0.z, r0.w);
            unpack2(acc[j][2], r1.x, r1.y);
            unpack2(acc[j][3], r1.z, r1.w);
            float4* op =
                reinterpret_cast<float4*>(out + (orow0 + j) * OUT_F + cg * 8);
            op[0] = r0;
            op[1] = r1;
        }
    }
}

// ---------------------------------------------------------------------------
extern "C" void kernel_launch(void* const* d_in, const int* in_sizes, int n_in,
                              void* d_out, int out_size) {
    const float* T  = (const float*)d_in[0];
    const float* O1 = (const float*)d_in[1];
    const float* O2 = (const float*)d_in[2];
    const float* W  = (const float*)d_in[3];
    const float* s  = (const float*)d_in[4];
    float* out = (float*)d_out;

    cudaFuncSetAttribute(fused_attention_kernel,
                         cudaFuncAttributeMaxDynamicSharedMemorySize, SMEM_BYTES);

    compute_u_kernel<<<1, IN_F>>>(W, s);

    const int nblocks = NROWS / RPB;  // 200000 / 64 = 3125 exactly
    fused_attention_kernel<<<nblocks, THREADS, SMEM_BYTES>>>(T, O1, O2, W, out);
}

// round 2
// speedup vs baseline: 1.4364x; 1.4364x over previous
#include <cuda_runtime.h>
#include <cstdint>

#define LRELU_ALPHA 0.2f
#define NROWS 200000
#define IN_F  256
#define OUT_F 128

#define RPB      64
#define THREADS  128
#define MSTRIDE  260   // 260 % 32 == 4 -> row r starts at bank 4r (mod 32); 16B aligned
#define SMEM_FLOATS (2 * IN_F + RPB * MSTRIDE)
#define SMEM_BYTES  (SMEM_FLOATS * 4)

__device__ float g_u[2 * IN_F];   // u_top | u_bot

// ---------------- packed fp32x2 helpers (Blackwell FFMA2 via PTX) ----------
typedef unsigned long long ull;
__device__ __forceinline__ ull pack2(float lo, float hi) {
    ull r;
    asm("mov.b64 %0, {%1, %2};" : "=l"(r) : "f"(lo), "f"(hi));
    return r;
}
__device__ __forceinline__ void ffma2(ull& d, ull a, ull b) {
    asm("fma.rn.f32x2 %0, %1, %2, %0;" : "+l"(d) : "l"(a), "l"(b));
}
__device__ __forceinline__ void unpack2(ull v, float& lo, float& hi) {
    asm("mov.b64 {%0, %1}, %2;" : "=f"(lo), "=f"(hi) : "l"(v));
}

__device__ __forceinline__ float dot8(float4 x0, float4 x1, float4 y0, float4 y1) {
    float d = 0.f;
    d = fmaf(x0.x, y0.x, d); d = fmaf(x0.y, y0.y, d);
    d = fmaf(x0.z, y0.z, d); d = fmaf(x0.w, y0.w, d);
    d = fmaf(x1.x, y1.x, d); d = fmaf(x1.y, y1.y, d);
    d = fmaf(x1.z, y1.z, d); d = fmaf(x1.w, y1.w, d);
    return d;
}

// ---------------------------------------------------------------------------
__global__ void compute_u_kernel(const float* __restrict__ W,
                                 const float* __restrict__ s) {
    int i = threadIdx.x;  // 0..255
    const float* wrow = W + i * OUT_F;
    float ut = 0.f, ub = 0.f;
#pragma unroll 8
    for (int j = 0; j < OUT_F; ++j) {
        float w = wrow[j];
        ut = fmaf(w, s[j], ut);
        ub = fmaf(w, s[OUT_F + j], ub);
    }
    g_u[i] = ut;
    g_u[IN_F + i] = ub;
}

// ---------------------------------------------------------------------------
// Fused: logits -> softmax -> mix (smem) -> mix @ W
// 64 rows/block, 128 threads. Phase 2: 8x8 outputs/thread, warp covers
// 64 rows x 32 cols -> 1 W wavefront + 2 mix wavefronts per k per warp.
// ---------------------------------------------------------------------------
__global__ __launch_bounds__(THREADS, 3)
void fused_attention_kernel(const float* __restrict__ T,
                            const float* __restrict__ O1,
                            const float* __restrict__ O2,
                            const float* __restrict__ W,
                            float* __restrict__ out) {
    extern __shared__ float sm[];
    float* s_u   = sm;            // 512 floats
    float* s_mix = sm + 2 * IN_F; // RPB x MSTRIDE

    const int tid  = threadIdx.x;
    const int lane = tid & 31;
    const int w    = tid >> 5;    // 0..3
    const int row0 = blockIdx.x * RPB;

    for (int i = tid; i < 2 * IN_F; i += THREADS) s_u[i] = g_u[i];
    __syncthreads();

    // ---------------- Phase 1: attention + mixed rows (16 rows per warp) ----
    {
        const float4* up = reinterpret_cast<const float4*>(s_u) + lane * 2;
        const float4 ut0 = up[0], ut1 = up[1];
        const float4* bp = reinterpret_cast<const float4*>(s_u + IN_F) + lane * 2;
        const float4 ub0 = bp[0], ub1 = bp[1];

        // process rows in pairs: 12 independent LDG.128 in flight
#pragma unroll 2
        for (int rr = 0; rr < 16; rr += 2) {
            const int rA = w * 16 + rr;
            const int rB = rA + 1;
            const long long gA = (long long)(row0 + rA);
            const long long gB = (long long)(row0 + rB);

            const float4* tA = reinterpret_cast<const float4*>(T  + gA * IN_F) + lane * 2;
            const float4* aA = reinterpret_cast<const float4*>(O1 + gA * IN_F) + lane * 2;
            const float4* bA = reinterpret_cast<const float4*>(O2 + gA * IN_F) + lane * 2;
            const float4* tB = reinterpret_cast<const float4*>(T  + gB * IN_F) + lane * 2;
            const float4* aB = reinterpret_cast<const float4*>(O1 + gB * IN_F) + lane * 2;
            const float4* bB = reinterpret_cast<const float4*>(O2 + gB * IN_F) + lane * 2;

            float4 tA0 = tA[0], tA1 = tA[1];
            float4 aA0 = aA[0], aA1 = aA[1];
            float4 bA0 = bA[0], bA1 = bA[1];
            float4 tB0 = tB[0], tB1 = tB[1];
            float4 aB0 = aB[0], aB1 = aB[1];
            float4 bB0 = bB[0], bB1 = bB[1];

            float dttA = dot8(tA0, tA1, ut0, ut1);
            float dtbA = dot8(tA0, tA1, ub0, ub1);
            float d1A  = dot8(aA0, aA1, ub0, ub1);
            float d2A  = dot8(bA0, bA1, ub0, ub1);
            float dttB = dot8(tB0, tB1, ut0, ut1);
            float dtbB = dot8(tB0, tB1, ub0, ub1);
            float d1B  = dot8(aB0, aB1, ub0, ub1);
            float d2B  = dot8(bB0, bB1, ub0, ub1);

#pragma unroll
            for (int off = 16; off; off >>= 1) {
                dttA += __shfl_xor_sync(0xffffffffu, dttA, off);
                dtbA += __shfl_xor_sync(0xffffffffu, dtbA, off);
                d1A  += __shfl_xor_sync(0xffffffffu, d1A,  off);
                d2A  += __shfl_xor_sync(0xffffffffu, d2A,  off);
                dttB += __shfl_xor_sync(0xffffffffu, dttB, off);
                dtbB += __shfl_xor_sync(0xffffffffu, dtbB, off);
                d1B  += __shfl_xor_sync(0xffffffffu, d1B,  off);
                d2B  += __shfl_xor_sync(0xffffffffu, d2B,  off);
            }

            // row A softmax + mix
            {
                float e0 = dttA + dtbA, e1 = dttA + d1A, e2 = dttA + d2A;
                e0 = e0 > 0.f ? e0 : LRELU_ALPHA * e0;
                e1 = e1 > 0.f ? e1 : LRELU_ALPHA * e1;
                e2 = e2 > 0.f ? e2 : LRELU_ALPHA * e2;
                float m = fmaxf(e0, fmaxf(e1, e2));
                float w0 = expf(e0 - m), w1 = expf(e1 - m), w2 = expf(e2 - m);
                float inv = 1.f / (w0 + w1 + w2);
                w0 *= inv; w1 *= inv; w2 *= inv;
                float4 m0, m1;
                m0.x = fmaf(w0, tA0.x, fmaf(w1, aA0.x, w2 * bA0.x));
                m0.y = fmaf(w0, tA0.y, fmaf(w1, aA0.y, w2 * bA0.y));
                m0.z = fmaf(w0, tA0.z, fmaf(w1, aA0.z, w2 * bA0.z));
                m0.w = fmaf(w0, tA0.w, fmaf(w1, aA0.w, w2 * bA0.w));
                m1.x = fmaf(w0, tA1.x, fmaf(w1, aA1.x, w2 * bA1.x));
                m1.y = fmaf(w0, tA1.y, fmaf(w1, aA1.y, w2 * bA1.y));
                m1.z = fmaf(w0, tA1.z, fmaf(w1, aA1.z, w2 * bA1.z));
                m1.w = fmaf(w0, tA1.w, fmaf(w1, aA1.w, w2 * bA1.w));
                float4* dst = reinterpret_cast<float4*>(&s_mix[rA * MSTRIDE + lane * 8]);
                dst[0] = m0; dst[1] = m1;
            }
            // row B softmax + mix
            {
                float e0 = dttB + dtbB, e1 = dttB + d1B, e2 = dttB + d2B;
                e0 = e0 > 0.f ? e0 : LRELU_ALPHA * e0;
                e1 = e1 > 0.f ? e1 : LRELU_ALPHA * e1;
                e2 = e2 > 0.f ? e2 : LRELU_ALPHA * e2;
                float m = fmaxf(e0, fmaxf(e1, e2));
                float w0 = expf(e0 - m), w1 = expf(e1 - m), w2 = expf(e2 - m);
                float inv = 1.f / (w0 + w1 + w2);
                w0 *= inv; w1 *= inv; w2 *= inv;
                float4 m0, m1;
                m0.x = fmaf(w0, tB0.x, fmaf(w1, aB0.x, w2 * bB0.x));
                m0.y = fmaf(w0, tB0.y, fmaf(w1, aB0.y, w2 * bB0.y));
                m0.z = fmaf(w0, tB0.z, fmaf(w1, aB0.z, w2 * bB0.z));
                m0.w = fmaf(w0, tB0.w, fmaf(w1, aB0.w, w2 * bB0.w));
                m1.x = fmaf(w0, tB1.x, fmaf(w1, aB1.x, w2 * bB1.x));
                m1.y = fmaf(w0, tB1.y, fmaf(w1, aB1.y, w2 * bB1.y));
                m1.z = fmaf(w0, tB1.z, fmaf(w1, aB1.z, w2 * bB1.z));
                m1.w = fmaf(w0, tB1.w, fmaf(w1, aB1.w, w2 * bB1.w));
                float4* dst = reinterpret_cast<float4*>(&s_mix[rB * MSTRIDE + lane * 8]);
                dst[0] = m0; dst[1] = m1;
            }
        }
    }
    __syncthreads();

    // ---------------- Phase 2: out[64x128] = mix[64x256] @ W[256x128] -------
    // thread (rg = lane&7, cg = w*4 + lane>>3) owns rows {rg + 8j}, cols cg*8..+7
    // per k per warp: W = 128B (1 wavefront, broadcast x8), mix = 256B.
    {
        const int rg = lane & 7;
        const int cg = w * 4 + (lane >> 3);

        ull acc[8][4];
#pragma unroll
        for (int j = 0; j < 8; ++j)
#pragma unroll
            for (int c = 0; c < 4; ++c) acc[j][c] = 0ULL;

        const float* wcol = W + cg * 8;

        for (int k = 0; k < IN_F; k += 4) {
            float4 mv[8];
#pragma unroll
            for (int j = 0; j < 8; ++j)
                mv[j] = *reinterpret_cast<const float4*>(
                    &s_mix[(rg + 8 * j) * MSTRIDE + k]);
#pragma unroll
            for (int kk = 0; kk < 4; ++kk) {
                const float4* wp =
                    reinterpret_cast<const float4*>(wcol + (k + kk) * OUT_F);
                float4 w0 = wp[0], w1 = wp[1];
                ull wv0 = pack2(w0.x, w0.y);
                ull wv1 = pack2(w0.z, w0.w);
                ull wv2 = pack2(w1.x, w1.y);
                ull wv3 = pack2(w1.z, w1.w);
#pragma unroll
                for (int j = 0; j < 8; ++j) {
                    float mval = (kk == 0) ? mv[j].x
                               : (kk == 1) ? mv[j].y
                               : (kk == 2) ? mv[j].z
                                           : mv[j].w;
                    ull mp = pack2(mval, mval);
                    ffma2(acc[j][0], mp, wv0);
                    ffma2(acc[j][1], mp, wv1);
                    ffma2(acc[j][2], mp, wv2);
                    ffma2(acc[j][3], mp, wv3);
                }
            }
        }

#pragma unroll
        for (int j = 0; j < 8; ++j) {
            const long long orow = (long long)(row0 + rg + 8 * j);
            float4 r0, r1;
            unpack2(acc[j][0], r0.x, r0.y);
            unpack2(acc[j][1], r0.z, r0.w);
            unpack2(acc[j][2], r1.x, r1.y);
            unpack2(acc[j][3], r1.z, r1.w);
            float4* op =
                reinterpret_cast<float4*>(out + orow * OUT_F + cg * 8);
            op[0] = r0;
            op[1] = r1;
        }
    }
}

// ---------------------------------------------------------------------------
extern "C" void kernel_launch(void* const* d_in, const int* in_sizes, int n_in,
                              void* d_out, int out_size) {
    const float* T  = (const float*)d_in[0];
    const float* O1 = (const float*)d_in[1];
    const float* O2 = (const float*)d_in[2];
    const float* W  = (const float*)d_in[3];
    const float* s  = (const float*)d_in[4];
    float* out = (float*)d_out;

    cudaFuncSetAttribute(fused_attention_kernel,
                         cudaFuncAttributeMaxDynamicSharedMemorySize, SMEM_BYTES);

    compute_u_kernel<<<1, IN_F>>>(W, s);

    const int nblocks = NROWS / RPB;  // 3125
    fused_attention_kernel<<<nblocks, THREADS, SMEM_BYTES>>>(T, O1, O2, W, out);
}

// round 4
// speedup vs baseline: 1.5418x; 1.0734x over previous
#include <cuda_runtime.h>
#include <cstdint>

#define LRELU_ALPHA 0.2f
#define NROWS 200000
#define IN_F  256
#define OUT_F 128

#define RPB      40            // rows per block (200000 / 40 = 5000 exact)
#define THREADS  128
#define MSTRIDE  260           // 260 % 32 == 4 -> conflict-free row starts; 16B aligned
#define SMEM_FLOATS (2 * IN_F + RPB * MSTRIDE)
#define SMEM_BYTES  (SMEM_FLOATS * 4)   // ~43.6 KB

__device__ float g_u[2 * IN_F];   // u_top | u_bot

// ---------------- packed fp32x2 helpers (Blackwell FFMA2 via PTX) ----------
typedef unsigned long long ull;
__device__ __forceinline__ ull pack2(float lo, float hi) {
    ull r;
    asm("mov.b64 %0, {%1, %2};" : "=l"(r) : "f"(lo), "f"(hi));
    return r;
}
__device__ __forceinline__ void ffma2(ull& d, ull a, ull b) {
    asm("fma.rn.f32x2 %0, %1, %2, %0;" : "+l"(d) : "l"(a), "l"(b));
}
__device__ __forceinline__ void unpack2(ull v, float& lo, float& hi) {
    asm("mov.b64 {%0, %1}, %2;" : "=f"(lo), "=f"(hi) : "l"(v));
}

__device__ __forceinline__ float dot8(float4 x0, float4 x1, float4 y0, float4 y1) {
    float d = 0.f;
    d = fmaf(x0.x, y0.x, d); d = fmaf(x0.y, y0.y, d);
    d = fmaf(x0.z, y0.z, d); d = fmaf(x0.w, y0.w, d);
    d = fmaf(x1.x, y1.x, d); d = fmaf(x1.y, y1.y, d);
    d = fmaf(x1.z, y1.z, d); d = fmaf(x1.w, y1.w, d);
    return d;
}

// ---------------------------------------------------------------------------
__global__ void compute_u_kernel(const float* __restrict__ W,
                                 const float* __restrict__ s) {
    int i = threadIdx.x;  // 0..255
    const float* wrow = W + i * OUT_F;
    float ut = 0.f, ub = 0.f;
#pragma unroll 8
    for (int j = 0; j < OUT_F; ++j) {
        float w = wrow[j];
        ut = fmaf(w, s[j], ut);
        ub = fmaf(w, s[OUT_F + j], ub);
    }
    g_u[i] = ut;
    g_u[IN_F + i] = ub;
}

// ---------------------------------------------------------------------------
// Fused: logits -> softmax -> mix (smem) -> mix @ W
// 40 rows/block, 128 threads.
// Phase 1: 10 rows per warp (5 pairs), shuffle-butterfly reductions.
// Phase 2: 5x8 outputs/thread; warp covers 40 rows x 32 cols.
// ---------------------------------------------------------------------------
__global__ __launch_bounds__(THREADS, 4)
void fused_attention_kernel(const float* __restrict__ T,
                            const float* __restrict__ O1,
                            const float* __restrict__ O2,
                            const float* __restrict__ W,
                            float* __restrict__ out) {
    extern __shared__ float sm[];
    float* s_u   = sm;            // 512 floats
    float* s_mix = sm + 2 * IN_F; // RPB x MSTRIDE

    const int tid  = threadIdx.x;
    const int lane = tid & 31;
    const int w    = tid >> 5;    // 0..3
    const int row0 = blockIdx.x * RPB;

    for (int i = tid; i < 2 * IN_F; i += THREADS) s_u[i] = g_u[i];
    __syncthreads();

    // ---------------- Phase 1: attention + mixed rows (10 rows per warp) ----
    {
        const float4* up = reinterpret_cast<const float4*>(s_u) + lane * 2;
        const float4 ut0 = up[0], ut1 = up[1];
        const float4* bp = reinterpret_cast<const float4*>(s_u + IN_F) + lane * 2;
        const float4 ub0 = bp[0], ub1 = bp[1];

#pragma unroll 1
        for (int rr = 0; rr < 10; rr += 2) {
            const int rA = w * 10 + rr;
            const int rB = rA + 1;
            const long long gA = (long long)(row0 + rA);
            const long long gB = (long long)(row0 + rB);

            const float4* tA = reinterpret_cast<const float4*>(T  + gA * IN_F) + lane * 2;
            const float4* aA = reinterpret_cast<const float4*>(O1 + gA * IN_F) + lane * 2;
            const float4* bA = reinterpret_cast<const float4*>(O2 + gA * IN_F) + lane * 2;
            const float4* tB = reinterpret_cast<const float4*>(T  + gB * IN_F) + lane * 2;
            const float4* aB = reinterpret_cast<const float4*>(O1 + gB * IN_F) + lane * 2;
            const float4* bB = reinterpret_cast<const float4*>(O2 + gB * IN_F) + lane * 2;

            float4 tA0 = tA[0], tA1 = tA[1];
            float4 aA0 = aA[0], aA1 = aA[1];
            float4 bA0 = bA[0], bA1 = bA[1];
            float4 tB0 = tB[0], tB1 = tB[1];
            float4 aB0 = aB[0], aB1 = aB[1];
            float4 bB0 = bB[0], bB1 = bB[1];

            float dttA = dot8(tA0, tA1, ut0, ut1);
            float dtbA = dot8(tA0, tA1, ub0, ub1);
            float d1A  = dot8(aA0, aA1, ub0, ub1);
            float d2A  = dot8(bA0, bA1, ub0, ub1);
            float dttB = dot8(tB0, tB1, ut0, ut1);
            float dtbB = dot8(tB0, tB1, ub0, ub1);
            float d1B  = dot8(aB0, aB1, ub0, ub1);
            float d2B  = dot8(bB0, bB1, ub0, ub1);

#pragma unroll
            for (int off = 16; off; off >>= 1) {
                dttA += __shfl_xor_sync(0xffffffffu, dttA, off);
                dtbA += __shfl_xor_sync(0xffffffffu, dtbA, off);
                d1A  += __shfl_xor_sync(0xffffffffu, d1A,  off);
                d2A  += __shfl_xor_sync(0xffffffffu, d2A,  off);
                dttB += __shfl_xor_sync(0xffffffffu, dttB, off);
                dtbB += __shfl_xor_sync(0xffffffffu, dtbB, off);
                d1B  += __shfl_xor_sync(0xffffffffu, d1B,  off);
                d2B  += __shfl_xor_sync(0xffffffffu, d2B,  off);
            }

            // row A softmax + mix
            {
                float e0 = dttA + dtbA, e1 = dttA + d1A, e2 = dttA + d2A;
                e0 = e0 > 0.f ? e0 : LRELU_ALPHA * e0;
                e1 = e1 > 0.f ? e1 : LRELU_ALPHA * e1;
                e2 = e2 > 0.f ? e2 : LRELU_ALPHA * e2;
                float m = fmaxf(e0, fmaxf(e1, e2));
                float w0 = __expf(e0 - m), w1 = __expf(e1 - m), w2 = __expf(e2 - m);
                float inv = 1.f / (w0 + w1 + w2);
                w0 *= inv; w1 *= inv; w2 *= inv;
                float4 m0, m1;
                m0.x = fmaf(w0, tA0.x, fmaf(w1, aA0.x, w2 * bA0.x));
                m0.y = fmaf(w0, tA0.y, fmaf(w1, aA0.y, w2 * bA0.y));
                m0.z = fmaf(w0, tA0.z, fmaf(w1, aA0.z, w2 * bA0.z));
                m0.w = fmaf(w0, tA0.w, fmaf(w1, aA0.w, w2 * bA0.w));
                m1.x = fmaf(w0, tA1.x, fmaf(w1, aA1.x, w2 * bA1.x));
                m1.y = fmaf(w0, tA1.y, fmaf(w1, aA1.y, w2 * bA1.y));
                m1.z = fmaf(w0, tA1.z, fmaf(w1, aA1.z, w2 * bA1.z));
                m1.w = fmaf(w0, tA1.w, fmaf(w1, aA1.w, w2 * bA1.w));
                float4* dst = reinterpret_cast<float4*>(&s_mix[rA * MSTRIDE + lane * 8]);
                dst[0] = m0; dst[1] = m1;
            }
            // row B softmax + mix
            {
                float e0 = dttB + dtbB, e1 = dttB + d1B, e2 = dttB + d2B;
                e0 = e0 > 0.f ? e0 : LRELU_ALPHA * e0;
                e1 = e1 > 0.f ? e1 : LRELU_ALPHA * e1;
                e2 = e2 > 0.f ? e2 : LRELU_ALPHA * e2;
                float m = fmaxf(e0, fmaxf(e1, e2));
                float w0 = __expf(e0 - m), w1 = __expf(e1 - m), w2 = __expf(e2 - m);
                float inv = 1.f / (w0 + w1 + w2);
                w0 *= inv; w1 *= inv; w2 *= inv;
                float4 m0, m1;
                m0.x = fmaf(w0, tB0.x, fmaf(w1, aB0.x, w2 * bB0.x));
                m0.y = fmaf(w0, tB0.y, fmaf(w1, aB0.y, w2 * bB0.y));
                m0.z = fmaf(w0, tB0.z, fmaf(w1, aB0.z, w2 * bB0.z));
                m0.w = fmaf(w0, tB0.w, fmaf(w1, aB0.w, w2 * bB0.w));
                m1.x = fmaf(w0, tB1.x, fmaf(w1, aB1.x, w2 * bB1.x));
                m1.y = fmaf(w0, tB1.y, fmaf(w1, aB1.y, w2 * bB1.y));
                m1.z = fmaf(w0, tB1.z, fmaf(w1, aB1.z, w2 * bB1.z));
                m1.w = fmaf(w0, tB1.w, fmaf(w1, aB1.w, w2 * bB1.w));
                float4* dst = reinterpret_cast<float4*>(&s_mix[rB * MSTRIDE + lane * 8]);
                dst[0] = m0; dst[1] = m1;
            }
        }
    }
    __syncthreads();

    // ---------------- Phase 2: out[40x128] = mix[40x256] @ W[256x128] -------
    // thread (rg = lane&7, cg = w*4 + lane>>3) owns rows {rg + 8j, j<5},
    // cols cg*8..+7. Per k per warp: W = 1 broadcast wavefront, mix = 2.
    {
        const int rg = lane & 7;
        const int cg = w * 4 + (lane >> 3);

        ull acc[5][4];
#pragma unroll
        for (int j = 0; j < 5; ++j)
#pragma unroll
            for (int c = 0; c < 4; ++c) acc[j][c] = 0ULL;

        const float* wcol = W + cg * 8;

#pragma unroll 2
        for (int k = 0; k < IN_F; k += 4) {
            float4 mv[5];
#pragma unroll
            for (int j = 0; j < 5; ++j)
                mv[j] = *reinterpret_cast<const float4*>(
                    &s_mix[(rg + 8 * j) * MSTRIDE + k]);
#pragma unroll
            for (int kk = 0; kk < 4; ++kk) {
                const float4* wp =
                    reinterpret_cast<const float4*>(wcol + (k + kk) * OUT_F);
                float4 w0 = wp[0], w1 = wp[1];
                ull wv0 = pack2(w0.x, w0.y);
                ull wv1 = pack2(w0.z, w0.w);
                ull wv2 = pack2(w1.x, w1.y);
                ull wv3 = pack2(w1.z, w1.w);
#pragma unroll
                for (int j = 0; j < 5; ++j) {
                    float mval = (kk == 0) ? mv[j].x
                               : (kk == 1) ? mv[j].y
                               : (kk == 2) ? mv[j].z
                                           : mv[j].w;
                    ull mp = pack2(mval, mval);
                    ffma2(acc[j][0], mp, wv0);
                    ffma2(acc[j][1], mp, wv1);
                    ffma2(acc[j][2], mp, wv2);
                    ffma2(acc[j][3], mp, wv3);
                }
            }
        }

#pragma unroll
        for (int j = 0; j < 5; ++j) {
            const long long orow = (long long)(row0 + rg + 8 * j);
            float4 r0, r1;
            unpack2(acc[j][0], r0.x, r0.y);
            unpack2(acc[j][1], r0.z, r0.w);
            unpack2(acc[j][2], r1.x, r1.y);
            unpack2(acc[j][3], r1.z, r1.w);
            float4* op =
                reinterpret_cast<float4*>(out + orow * OUT_F + cg * 8);
            op[0] = r0;
            op[1] = r1;
        }
    }
}

// ---------------------------------------------------------------------------
extern "C" void kernel_launch(void* const* d_in, const int* in_sizes, int n_in,
                              void* d_out, int out_size) {
    const float* T  = (const float*)d_in[0];
    const float* O1 = (const float*)d_in[1];
    const float* O2 = (const float*)d_in[2];
    const float* W  = (const float*)d_in[3];
    const float* s  = (const float*)d_in[4];
    float* out = (float*)d_out;

    cudaFuncSetAttribute(fused_attention_kernel,
                         cudaFuncAttributeMaxDynamicSharedMemorySize, SMEM_BYTES);

    compute_u_kernel<<<1, IN_F>>>(W, s);

    const int nblocks = NROWS / RPB;  // 5000
    fused_attention_kernel<<<nblocks, THREADS, SMEM_BYTES>>>(T, O1, O2, W, out);
}

// round 7
// speedup vs baseline: 2.5868x; 1.6777x over previous
#include <cuda_runtime.h>
#include <cuda_bf16.h>
#include <cstdint>

#define LRELU_ALPHA 0.2f
#define NROWS 200000
#define IN_F  256
#define OUT_F 128

#define RPB      48                      // rows per CTA (3 mma row-tiles)
#define THREADS  128                     // 4 warps
#define NBLK     ((NROWS + RPB - 1) / RPB)   // 4167

#define PSTRIDE  132                     // u32 (bf16-pairs) per row: 128 + 4 pad
#define AHI_OFF  512                     // after u vectors (512 floats)
#define ALO_OFF  (AHI_OFF + RPB * PSTRIDE)
#define SMEM_U32S (ALO_OFF + RPB * PSTRIDE)
#define SMEM_BYTES (SMEM_U32S * 4)       // 2048 + 2*25344 = 52736 B -> 4 CTAs/SM

__device__ float g_u[2 * IN_F];          // u_top | u_bot
// B fragments, fragment-ordered: [kstep s(16)][ntile(16)][lane(32)] -> {b0,b1}
__device__ uint2 g_Bhi[16 * 16 * 32];
__device__ uint2 g_Blo[16 * 16 * 32];

// ---------------------------------------------------------------------------
__device__ __forceinline__ uint32_t bfpair(float lo_elem, float hi_elem) {
    // low 16 bits <- first arg (even k), high 16 <- second (odd k)
    __nv_bfloat162 h = __floats2bfloat162_rn(lo_elem, hi_elem);
    return *reinterpret_cast<uint32_t*>(&h);
}

__device__ __forceinline__ float dot8(float4 x0, float4 x1, float4 y0, float4 y1) {
    float d = 0.f;
    d = fmaf(x0.x, y0.x, d); d = fmaf(x0.y, y0.y, d);
    d = fmaf(x0.z, y0.z, d); d = fmaf(x0.w, y0.w, d);
    d = fmaf(x1.x, y1.x, d); d = fmaf(x1.y, y1.y, d);
    d = fmaf(x1.z, y1.z, d); d = fmaf(x1.w, y1.w, d);
    return d;
}

#define MMA_BF16(d, a, b0v, b1v)                                               \
    asm volatile(                                                              \
        "mma.sync.aligned.m16n8k16.row.col.f32.bf16.bf16.f32 "                 \
        "{%0,%1,%2,%3}, {%4,%5,%6,%7}, {%8,%9}, {%0,%1,%2,%3};"                \
        : "+f"(d[0]), "+f"(d[1]), "+f"(d[2]), "+f"(d[3])                       \
        : "r"(a[0]), "r"(a[1]), "r"(a[2]), "r"(a[3]), "r"(b0v), "r"(b1v))

// ---------------------------------------------------------------------------
// Prep kernels
// ---------------------------------------------------------------------------
__global__ void compute_u_kernel(const float* __restrict__ W,
                                 const float* __restrict__ s) {
    int i = threadIdx.x;  // 0..255 (k)
    const float* wrow = W + i * OUT_F;
    float ut = 0.f, ub = 0.f;
#pragma unroll 8
    for (int j = 0; j < OUT_F; ++j) {
        float w = wrow[j];
        ut = fmaf(w, s[j], ut);
        ub = fmaf(w, s[OUT_F + j], ub);
    }
    g_u[i] = ut;
    g_u[IN_F + i] = ub;
}

// Pack W[k][n] into m16n8k16 B-fragment order (hi and lo bf16 parts).
__global__ void pack_b_kernel(const float* __restrict__ W) {
    int nt = blockIdx.x;      // 0..15 (n tile of 8)
    int s  = blockIdx.y;      // 0..15 (k step of 16)
    int lane = threadIdx.x;   // 0..31
    int g = lane >> 2, t = lane & 3;
    int n = nt * 8 + g;
    uint32_t hv[2], lv[2];
#pragma unroll
    for (int rg = 0; rg < 2; ++rg) {
        int k = s * 16 + rg * 8 + 2 * t;
        float w0 = W[k * OUT_F + n];
        float w1 = W[(k + 1) * OUT_F + n];
        float h0 = __bfloat162float(__float2bfloat16_rn(w0));
        float h1 = __bfloat162float(__float2bfloat16_rn(w1));
        hv[rg] = bfpair(h0, h1);
        lv[rg] = bfpair(w0 - h0, w1 - h1);
    }
    int idx = (s * 16 + nt) * 32 + lane;
    g_Bhi[idx] = make_uint2(hv[0], hv[1]);
    g_Blo[idx] = make_uint2(lv[0], lv[1]);
}

// ---------------------------------------------------------------------------
// Fused kernel: logits -> softmax -> mix (bf16 hi/lo frag layout in smem)
//               -> HMMA GEMM (mix @ W) -> out
// ---------------------------------------------------------------------------
__global__ __launch_bounds__(THREADS, 4)
void fused_attention_kernel(const float* __restrict__ T,
                            const float* __restrict__ O1,
                            const float* __restrict__ O2,
                            float* __restrict__ out) {
    extern __shared__ char smem_raw[];
    uint32_t* s32 = reinterpret_cast<uint32_t*>(smem_raw);
    float* s_u = reinterpret_cast<float*>(smem_raw);
    uint32_t* smA_hi = s32 + AHI_OFF;
    uint32_t* smA_lo = s32 + ALO_OFF;

    const int tid  = threadIdx.x;
    const int lane = tid & 31;
    const int w    = tid >> 5;    // 0..3
    const int row0 = blockIdx.x * RPB;

    for (int i = tid; i < 2 * IN_F; i += THREADS) s_u[i] = g_u[i];
    __syncthreads();

    // ---------------- Phase 1: attention + mixed rows (12 rows per warp) ----
    {
        const float4* up = reinterpret_cast<const float4*>(s_u) + lane * 2;
        const float4 ut0 = up[0], ut1 = up[1];
        const float4* bp = reinterpret_cast<const float4*>(s_u + IN_F) + lane * 2;
        const float4 ub0 = bp[0], ub1 = bp[1];

#pragma unroll 1
        for (int rr = 0; rr < 12; rr += 2) {
            const int rA = w * 12 + rr;
            const int rB = rA + 1;
            long long gA = (long long)(row0 + rA);
            long long gB = (long long)(row0 + rB);
            if (gA >= NROWS) gA = NROWS - 1;
            if (gB >= NROWS) gB = NROWS - 1;

            const float4* tA = reinterpret_cast<const float4*>(T  + gA * IN_F) + lane * 2;
            const float4* aA = reinterpret_cast<const float4*>(O1 + gA * IN_F) + lane * 2;
            const float4* bA = reinterpret_cast<const float4*>(O2 + gA * IN_F) + lane * 2;
            const float4* tB = reinterpret_cast<const float4*>(T  + gB * IN_F) + lane * 2;
            const float4* aB = reinterpret_cast<const float4*>(O1 + gB * IN_F) + lane * 2;
            const float4* bB = reinterpret_cast<const float4*>(O2 + gB * IN_F) + lane * 2;

            float4 tA0 = tA[0], tA1 = tA[1];
            float4 aA0 = aA[0], aA1 = aA[1];
            float4 bA0 = bA[0], bA1 = bA[1];
            float4 tB0 = tB[0], tB1 = tB[1];
            float4 aB0 = aB[0], aB1 = aB[1];
            float4 bB0 = bB[0], bB1 = bB[1];

            float dttA = dot8(tA0, tA1, ut0, ut1);
            float dtbA = dot8(tA0, tA1, ub0, ub1);
            float d1A  = dot8(aA0, aA1, ub0, ub1);
            float d2A  = dot8(bA0, bA1, ub0, ub1);
            float dttB = dot8(tB0, tB1, ut0, ut1);
            float dtbB = dot8(tB0, tB1, ub0, ub1);
            float d1B  = dot8(aB0, aB1, ub0, ub1);
            float d2B  = dot8(bB0, bB1, ub0, ub1);

#pragma unroll
            for (int off = 16; off; off >>= 1) {
                dttA += __shfl_xor_sync(0xffffffffu, dttA, off);
                dtbA += __shfl_xor_sync(0xffffffffu, dtbA, off);
                d1A  += __shfl_xor_sync(0xffffffffu, d1A,  off);
                d2A  += __shfl_xor_sync(0xffffffffu, d2A,  off);
                dttB += __shfl_xor_sync(0xffffffffu, dttB, off);
                dtbB += __shfl_xor_sync(0xffffffffu, dtbB, off);
                d1B  += __shfl_xor_sync(0xffffffffu, d1B,  off);
                d2B  += __shfl_xor_sync(0xffffffffu, d2B,  off);
            }

            // row A
            {
                float e0 = dttA + dtbA, e1 = dttA + d1A, e2 = dttA + d2A;
                e0 = e0 > 0.f ? e0 : LRELU_ALPHA * e0;
                e1 = e1 > 0.f ? e1 : LRELU_ALPHA * e1;
                e2 = e2 > 0.f ? e2 : LRELU_ALPHA * e2;
                float m = fmaxf(e0, fmaxf(e1, e2));
                float w0 = __expf(e0 - m), w1 = __expf(e1 - m), w2 = __expf(e2 - m);
                float inv = 1.f / (w0 + w1 + w2);
                w0 *= inv; w1 *= inv; w2 *= inv;
                float mx[8];
                mx[0] = fmaf(w0, tA0.x, fmaf(w1, aA0.x, w2 * bA0.x));
                mx[1] = fmaf(w0, tA0.y, fmaf(w1, aA0.y, w2 * bA0.y));
                mx[2] = fmaf(w0, tA0.z, fmaf(w1, aA0.z, w2 * bA0.z));
                mx[3] = fmaf(w0, tA0.w, fmaf(w1, aA0.w, w2 * bA0.w));
                mx[4] = fmaf(w0, tA1.x, fmaf(w1, aA1.x, w2 * bA1.x));
                mx[5] = fmaf(w0, tA1.y, fmaf(w1, aA1.y, w2 * bA1.y));
                mx[6] = fmaf(w0, tA1.z, fmaf(w1, aA1.z, w2 * bA1.z));
                mx[7] = fmaf(w0, tA1.w, fmaf(w1, aA1.w, w2 * bA1.w));
                float hf[8], lf[8];
#pragma unroll
                for (int i = 0; i < 8; ++i) {
                    hf[i] = __bfloat162float(__float2bfloat16_rn(mx[i]));
                    lf[i] = mx[i] - hf[i];
                }
                uint4 vh = make_uint4(bfpair(hf[0], hf[1]), bfpair(hf[2], hf[3]),
                                      bfpair(hf[4], hf[5]), bfpair(hf[6], hf[7]));
                uint4 vl = make_uint4(bfpair(lf[0], lf[1]), bfpair(lf[2], lf[3]),
                                      bfpair(lf[4], lf[5]), bfpair(lf[6], lf[7]));
                *reinterpret_cast<uint4*>(smA_hi + rA * PSTRIDE + lane * 4) = vh;
                *reinterpret_cast<uint4*>(smA_lo + rA * PSTRIDE + lane * 4) = vl;
            }
            // row B
            {
                float e0 = dttB + dtbB, e1 = dttB + d1B, e2 = dttB + d2B;
                e0 = e0 > 0.f ? e0 : LRELU_ALPHA * e0;
                e1 = e1 > 0.f ? e1 : LRELU_ALPHA * e1;
                e2 = e2 > 0.f ? e2 : LRELU_ALPHA * e2;
                float m = fmaxf(e0, fmaxf(e1, e2));
                float w0 = __expf(e0 - m), w1 = __expf(e1 - m), w2 = __expf(e2 - m);
                float inv = 1.f / (w0 + w1 + w2);
                w0 *= inv; w1 *= inv; w2 *= inv;
                float mx[8];
                mx[0] = fmaf(w0, tB0.x, fmaf(w1, aB0.x, w2 * bB0.x));
                mx[1] = fmaf(w0, tB0.y, fmaf(w1, aB0.y, w2 * bB0.y));
                mx[2] = fmaf(w0, tB0.z, fmaf(w1, aB0.z, w2 * bB0.z));
                mx[3] = fmaf(w0, tB0.w, fmaf(w1, aB0.w, w2 * bB0.w));
                mx[4] = fmaf(w0, tB1.x, fmaf(w1, aB1.x, w2 * bB1.x));
                mx[5] = fmaf(w0, tB1.y, fmaf(w1, aB1.y, w2 * bB1.y));
                mx[6] = fmaf(w0, tB1.z, fmaf(w1, aB1.z, w2 * bB1.z));
                mx[7] = fmaf(w0, tB1.w, fmaf(w1, aB1.w, w2 * bB1.w));
                float hf[8], lf[8];
#pragma unroll
                for (int i = 0; i < 8; ++i) {
                    hf[i] = __bfloat162float(__float2bfloat16_rn(mx[i]));
                    lf[i] = mx[i] - hf[i];
                }
                uint4 vh = make_uint4(bfpair(hf[0], hf[1]), bfpair(hf[2], hf[3]),
                                      bfpair(hf[4], hf[5]), bfpair(hf[6], hf[7]));
                uint4 vl = make_uint4(bfpair(lf[0], lf[1]), bfpair(lf[2], lf[3]),
                                      bfpair(lf[4], lf[5]), bfpair(lf[6], lf[7]));
                *reinterpret_cast<uint4*>(smA_hi + rB * PSTRIDE + lane * 4) = vh;
                *reinterpret_cast<uint4*>(smA_lo + rB * PSTRIDE + lane * 4) = vl;
            }
        }
    }
    __syncthreads();

    // ---------------- Phase 2: out[48x128] = mix @ W via HMMA ---------------
    // warp w owns cols [32w, 32w+32): 4 n-tiles; 3 row-tiles of 16.
    {
        const int g = lane >> 2;       // 0..7
        const int t = lane & 3;        // 0..3

        float acc[3][4][4];
#pragma unroll
        for (int r = 0; r < 3; ++r)
#pragma unroll
            for (int c = 0; c < 4; ++c)
#pragma unroll
                for (int i = 0; i < 4; ++i) acc[r][c][i] = 0.f;

#pragma unroll 1
        for (int s = 0; s < 16; ++s) {
            uint32_t ah[3][4], al[3][4];
#pragma unroll
            for (int r = 0; r < 3; ++r) {
                int base = (16 * r + g) * PSTRIDE + 8 * s + t;
                ah[r][0] = smA_hi[base];
                ah[r][1] = smA_hi[base + 8 * PSTRIDE];
                ah[r][2] = smA_hi[base + 4];
                ah[r][3] = smA_hi[base + 8 * PSTRIDE + 4];
                al[r][0] = smA_lo[base];
                al[r][1] = smA_lo[base + 8 * PSTRIDE];
                al[r][2] = smA_lo[base + 4];
                al[r][3] = smA_lo[base + 8 * PSTRIDE + 4];
            }
#pragma unroll
            for (int c = 0; c < 4; ++c) {
                int nt = w * 4 + c;
                uint2 bh = __ldg(&g_Bhi[(s * 16 + nt) * 32 + lane]);
                uint2 bl = __ldg(&g_Blo[(s * 16 + nt) * 32 + lane]);
#pragma unroll
                for (int r = 0; r < 3; ++r) {
                    MMA_BF16(acc[r][c], ah[r], bh.x, bh.y);
                    MMA_BF16(acc[r][c], al[r], bh.x, bh.y);
                    MMA_BF16(acc[r][c], ah[r], bl.x, bl.y);
                }
            }
        }

        // epilogue: d0,d1 -> (row 16r+g, cols 2t,2t+1); d2,d3 -> row +8
#pragma unroll
        for (int r = 0; r < 3; ++r) {
            const long long rowA = (long long)(row0 + 16 * r + g);
            const long long rowB = rowA + 8;
            const bool vA = rowA < NROWS;
            const bool vB = rowB < NROWS;
#pragma unroll
            for (int c = 0; c < 4; ++c) {
                const int col = 32 * w + 8 * c + 2 * t;
                if (vA) {
                    float2 v0 = make_float2(acc[r][c][0], acc[r][c][1]);
                    *reinterpret_cast<float2*>(out + rowA * OUT_F + col) = v0;
                }
                if (vB) {
                    float2 v1 = make_float2(acc[r][c][2], acc[r][c][3]);
                    *reinterpret_cast<float2*>(out + rowB * OUT_F + col) = v1;
                }
            }
        }
    }
}

// ---------------------------------------------------------------------------
extern "C" void kernel_launch(void* const* d_in, const int* in_sizes, int n_in,
                              void* d_out, int out_size) {
    const float* T  = (const float*)d_in[0];
    const float* O1 = (const float*)d_in[1];
    const float* O2 = (const float*)d_in[2];
    const float* W  = (const float*)d_in[3];
    const float* s  = (const float*)d_in[4];
    float* out = (float*)d_out;

    cudaFuncSetAttribute(fused_attention_kernel,
                         cudaFuncAttributeMaxDynamicSharedMemorySize, SMEM_BYTES);

    compute_u_kernel<<<1, IN_F>>>(W, s);
    pack_b_kernel<<<dim3(16, 16), 32>>>(W);
    fused_attention_kernel<<<NBLK, THREADS, SMEM_BYTES>>>(T, O1, O2, out);
}

// round 8
// speedup vs baseline: 2.8419x; 1.0986x over previous
#include <cuda_runtime.h>
#include <cuda_bf16.h>
#include <cstdint>

#define LRELU_ALPHA 0.2f
#define NROWS 200000
#define IN_F  256
#define OUT_F 128

#define RPB      48                      // rows per CTA (3 mma row-tiles)
#define THREADS  128                     // 4 warps
#define NBLK     ((NROWS + RPB - 1) / RPB)   // 4167

#define PSTRIDE  132                     // u32 (bf16-pairs) per row: 128 + 4 pad
#define AHI_OFF  512                     // after u vectors (512 floats)
#define ALO_OFF  (AHI_OFF + RPB * PSTRIDE)
#define SMEM_U32S (ALO_OFF + RPB * PSTRIDE)
#define SMEM_BYTES (SMEM_U32S * 4)       // 52736 B -> 4 CTAs/SM

__device__ float g_u[2 * IN_F];          // u_top | u_bot
// B fragments, fragment-ordered: [kstep s(16)][ntile(16)][lane(32)] -> {b0,b1}
__device__ uint2 g_Bhi[16 * 16 * 32];
__device__ uint2 g_Blo[16 * 16 * 32];

// ---------------------------------------------------------------------------
__device__ __forceinline__ uint32_t bfpair(float lo_elem, float hi_elem) {
    __nv_bfloat162 h = __floats2bfloat162_rn(lo_elem, hi_elem);
    return *reinterpret_cast<uint32_t*>(&h);
}

__device__ __forceinline__ float dot8(float4 x0, float4 x1, float4 y0, float4 y1) {
    float d = 0.f;
    d = fmaf(x0.x, y0.x, d); d = fmaf(x0.y, y0.y, d);
    d = fmaf(x0.z, y0.z, d); d = fmaf(x0.w, y0.w, d);
    d = fmaf(x1.x, y1.x, d); d = fmaf(x1.y, y1.y, d);
    d = fmaf(x1.z, y1.z, d); d = fmaf(x1.w, y1.w, d);
    return d;
}

#define MMA_BF16(d, a, b0v, b1v)                                               \
    asm volatile(                                                              \
        "mma.sync.aligned.m16n8k16.row.col.f32.bf16.bf16.f32 "                 \
        "{%0,%1,%2,%3}, {%4,%5,%6,%7}, {%8,%9}, {%0,%1,%2,%3};"                \
        : "+f"(d[0]), "+f"(d[1]), "+f"(d[2]), "+f"(d[3])                       \
        : "r"(a[0]), "r"(a[1]), "r"(a[2]), "r"(a[3]), "r"(b0v), "r"(b1v))

// ---------------------------------------------------------------------------
// Prep kernels
// ---------------------------------------------------------------------------
// One warp per output element i: lanes stride the 128-long dot, butterfly-reduce.
__global__ void compute_u_kernel(const float* __restrict__ W,
                                 const float* __restrict__ s) {
    const int gw   = blockIdx.x * 8 + (threadIdx.x >> 5);  // 0..255 (= i)
    const int lane = threadIdx.x & 31;
    const float* wrow = W + gw * OUT_F;
    float ut = 0.f, ub = 0.f;
#pragma unroll
    for (int jj = 0; jj < 4; ++jj) {
        int j = lane + jj * 32;
        float w = wrow[j];
        ut = fmaf(w, s[j], ut);
        ub = fmaf(w, s[OUT_F + j], ub);
    }
#pragma unroll
    for (int off = 16; off; off >>= 1) {
        ut += __shfl_xor_sync(0xffffffffu, ut, off);
        ub += __shfl_xor_sync(0xffffffffu, ub, off);
    }
    if (lane == 0) {
        g_u[gw] = ut;
        g_u[IN_F + gw] = ub;
    }
}

// Pack W[k][n] into m16n8k16 B-fragment order (hi and lo bf16 parts).
__global__ void pack_b_kernel(const float* __restrict__ W) {
    int nt = blockIdx.x;      // 0..15 (n tile of 8)
    int s  = blockIdx.y;      // 0..15 (k step of 16)
    int lane = threadIdx.x;   // 0..31
    int g = lane >> 2, t = lane & 3;
    int n = nt * 8 + g;
    uint32_t hv[2], lv[2];
#pragma unroll
    for (int rg = 0; rg < 2; ++rg) {
        int k = s * 16 + rg * 8 + 2 * t;
        float w0 = W[k * OUT_F + n];
        float w1 = W[(k + 1) * OUT_F + n];
        float h0 = __bfloat162float(__float2bfloat16_rn(w0));
        float h1 = __bfloat162float(__float2bfloat16_rn(w1));
        hv[rg] = bfpair(h0, h1);
        lv[rg] = bfpair(w0 - h0, w1 - h1);
    }
    int idx = (s * 16 + nt) * 32 + lane;
    g_Bhi[idx] = make_uint2(hv[0], hv[1]);
    g_Blo[idx] = make_uint2(lv[0], lv[1]);
}

// ---------------------------------------------------------------------------
// Fused kernel: logits -> softmax -> mix (bf16 hi/lo frag layout in smem)
//               -> HMMA GEMM (mix @ W) -> out
// ---------------------------------------------------------------------------
__global__ __launch_bounds__(THREADS, 4)
void fused_attention_kernel(const float* __restrict__ T,
                            const float* __restrict__ O1,
                            const float* __restrict__ O2,
                            float* __restrict__ out) {
    extern __shared__ char smem_raw[];
    uint32_t* s32 = reinterpret_cast<uint32_t*>(smem_raw);
    float* s_u = reinterpret_cast<float*>(smem_raw);
    uint32_t* smA_hi = s32 + AHI_OFF;
    uint32_t* smA_lo = s32 + ALO_OFF;

    const int tid  = threadIdx.x;
    const int lane = tid & 31;
    const int w    = tid >> 5;    // 0..3
    const int row0 = blockIdx.x * RPB;

    for (int i = tid; i < 2 * IN_F; i += THREADS) s_u[i] = g_u[i];
    __syncthreads();

    // ---------------- Phase 1: attention + mixed rows (12 rows per warp) ----
    {
        const float4* up = reinterpret_cast<const float4*>(s_u) + lane * 2;
        const float4 ut0 = up[0], ut1 = up[1];
        const float4* bp = reinterpret_cast<const float4*>(s_u + IN_F) + lane * 2;
        const float4 ub0 = bp[0], ub1 = bp[1];

#pragma unroll 1
        for (int rr = 0; rr < 12; rr += 2) {
            const int rA = w * 12 + rr;
            const int rB = rA + 1;
            long long gA = (long long)(row0 + rA);
            long long gB = (long long)(row0 + rB);
            if (gA >= NROWS) gA = NROWS - 1;
            if (gB >= NROWS) gB = NROWS - 1;

            const float4* tA = reinterpret_cast<const float4*>(T  + gA * IN_F) + lane * 2;
            const float4* aA = reinterpret_cast<const float4*>(O1 + gA * IN_F) + lane * 2;
            const float4* bA = reinterpret_cast<const float4*>(O2 + gA * IN_F) + lane * 2;
            const float4* tB = reinterpret_cast<const float4*>(T  + gB * IN_F) + lane * 2;
            const float4* aB = reinterpret_cast<const float4*>(O1 + gB * IN_F) + lane * 2;
            const float4* bB = reinterpret_cast<const float4*>(O2 + gB * IN_F) + lane * 2;

            float4 tA0 = tA[0], tA1 = tA[1];
            float4 aA0 = aA[0], aA1 = aA[1];
            float4 bA0 = bA[0], bA1 = bA[1];
            float4 tB0 = tB[0], tB1 = tB[1];
            float4 aB0 = aB[0], aB1 = aB[1];
            float4 bB0 = bB[0], bB1 = bB[1];

            float dttA = dot8(tA0, tA1, ut0, ut1);
            float dtbA = dot8(tA0, tA1, ub0, ub1);
            float d1A  = dot8(aA0, aA1, ub0, ub1);
            float d2A  = dot8(bA0, bA1, ub0, ub1);
            float dttB = dot8(tB0, tB1, ut0, ut1);
            float dtbB = dot8(tB0, tB1, ub0, ub1);
            float d1B  = dot8(aB0, aB1, ub0, ub1);
            float d2B  = dot8(bB0, bB1, ub0, ub1);

#pragma unroll
            for (int off = 16; off; off >>= 1) {
                dttA += __shfl_xor_sync(0xffffffffu, dttA, off);
                dtbA += __shfl_xor_sync(0xffffffffu, dtbA, off);
                d1A  += __shfl_xor_sync(0xffffffffu, d1A,  off);
                d2A  += __shfl_xor_sync(0xffffffffu, d2A,  off);
                dttB += __shfl_xor_sync(0xffffffffu, dttB, off);
                dtbB += __shfl_xor_sync(0xffffffffu, dtbB, off);
                d1B  += __shfl_xor_sync(0xffffffffu, d1B,  off);
                d2B  += __shfl_xor_sync(0xffffffffu, d2B,  off);
            }

            // row A
            {
                float e0 = dttA + dtbA, e1 = dttA + d1A, e2 = dttA + d2A;
                e0 = e0 > 0.f ? e0 : LRELU_ALPHA * e0;
                e1 = e1 > 0.f ? e1 : LRELU_ALPHA * e1;
                e2 = e2 > 0.f ? e2 : LRELU_ALPHA * e2;
                float m = fmaxf(e0, fmaxf(e1, e2));
                float w0 = __expf(e0 - m), w1 = __expf(e1 - m), w2 = __expf(e2 - m);
                float inv = 1.f / (w0 + w1 + w2);
                w0 *= inv; w1 *= inv; w2 *= inv;
                float mx[8];
                mx[0] = fmaf(w0, tA0.x, fmaf(w1, aA0.x, w2 * bA0.x));
                mx[1] = fmaf(w0, tA0.y, fmaf(w1, aA0.y, w2 * bA0.y));
                mx[2] = fmaf(w0, tA0.z, fmaf(w1, aA0.z, w2 * bA0.z));
                mx[3] = fmaf(w0, tA0.w, fmaf(w1, aA0.w, w2 * bA0.w));
                mx[4] = fmaf(w0, tA1.x, fmaf(w1, aA1.x, w2 * bA1.x));
                mx[5] = fmaf(w0, tA1.y, fmaf(w1, aA1.y, w2 * bA1.y));
                mx[6] = fmaf(w0, tA1.z, fmaf(w1, aA1.z, w2 * bA1.z));
                mx[7] = fmaf(w0, tA1.w, fmaf(w1, aA1.w, w2 * bA1.w));
                float hf[8], lf[8];
#pragma unroll
                for (int i = 0; i < 8; ++i) {
                    hf[i] = __bfloat162float(__float2bfloat16_rn(mx[i]));
                    lf[i] = mx[i] - hf[i];
                }
                uint4 vh = make_uint4(bfpair(hf[0], hf[1]), bfpair(hf[2], hf[3]),
                                      bfpair(hf[4], hf[5]), bfpair(hf[6], hf[7]));
                uint4 vl = make_uint4(bfpair(lf[0], lf[1]), bfpair(lf[2], lf[3]),
                                      bfpair(lf[4], lf[5]), bfpair(lf[6], lf[7]));
                *reinterpret_cast<uint4*>(smA_hi + rA * PSTRIDE + lane * 4) = vh;
                *reinterpret_cast<uint4*>(smA_lo + rA * PSTRIDE + lane * 4) = vl;
            }
            // row B
            {
                float e0 = dttB + dtbB, e1 = dttB + d1B, e2 = dttB + d2B;
                e0 = e0 > 0.f ? e0 : LRELU_ALPHA * e0;
                e1 = e1 > 0.f ? e1 : LRELU_ALPHA * e1;
                e2 = e2 > 0.f ? e2 : LRELU_ALPHA * e2;
                float m = fmaxf(e0, fmaxf(e1, e2));
                float w0 = __expf(e0 - m), w1 = __expf(e1 - m), w2 = __expf(e2 - m);
                float inv = 1.f / (w0 + w1 + w2);
                w0 *= inv; w1 *= inv; w2 *= inv;
                float mx[8];
                mx[0] = fmaf(w0, tB0.x, fmaf(w1, aB0.x, w2 * bB0.x));
                mx[1] = fmaf(w0, tB0.y, fmaf(w1, aB0.y, w2 * bB0.y));
                mx[2] = fmaf(w0, tB0.z, fmaf(w1, aB0.z, w2 * bB0.z));
                mx[3] = fmaf(w0, tB0.w, fmaf(w1, aB0.w, w2 * bB0.w));
                mx[4] = fmaf(w0, tB1.x, fmaf(w1, aB1.x, w2 * bB1.x));
                mx[5] = fmaf(w0, tB1.y, fmaf(w1, aB1.y, w2 * bB1.y));
                mx[6] = fmaf(w0, tB1.z, fmaf(w1, aB1.z, w2 * bB1.z));
                mx[7] = fmaf(w0, tB1.w, fmaf(w1, aB1.w, w2 * bB1.w));
                float hf[8], lf[8];
#pragma unroll
                for (int i = 0; i < 8; ++i) {
                    hf[i] = __bfloat162float(__float2bfloat16_rn(mx[i]));
                    lf[i] = mx[i] - hf[i];
                }
                uint4 vh = make_uint4(bfpair(hf[0], hf[1]), bfpair(hf[2], hf[3]),
                                      bfpair(hf[4], hf[5]), bfpair(hf[6], hf[7]));
                uint4 vl = make_uint4(bfpair(lf[0], lf[1]), bfpair(lf[2], lf[3]),
                                      bfpair(lf[4], lf[5]), bfpair(lf[6], lf[7]));
                *reinterpret_cast<uint4*>(smA_hi + rB * PSTRIDE + lane * 4) = vh;
                *reinterpret_cast<uint4*>(smA_lo + rB * PSTRIDE + lane * 4) = vl;
            }
        }
    }
    __syncthreads();

    // ---------------- Phase 2: out[48x128] = mix @ W via HMMA ---------------
    // warp w owns cols [32w, 32w+32): 4 n-tiles; 3 row-tiles of 16.
    {
        const int g = lane >> 2;       // 0..7
        const int t = lane & 3;        // 0..3

        float acc[3][4][4];
#pragma unroll
        for (int r = 0; r < 3; ++r)
#pragma unroll
            for (int c = 0; c < 4; ++c)
#pragma unroll
                for (int i = 0; i < 4; ++i) acc[r][c][i] = 0.f;

#pragma unroll 1
        for (int s = 0; s < 16; ++s) {
            uint32_t ah[3][4], al[3][4];
#pragma unroll
            for (int r = 0; r < 3; ++r) {
                int base = (16 * r + g) * PSTRIDE + 8 * s + t;
                ah[r][0] = smA_hi[base];
                ah[r][1] = smA_hi[base + 8 * PSTRIDE];
                ah[r][2] = smA_hi[base + 4];
                ah[r][3] = smA_hi[base + 8 * PSTRIDE + 4];
                al[r][0] = smA_lo[base];
                al[r][1] = smA_lo[base + 8 * PSTRIDE];
                al[r][2] = smA_lo[base + 4];
                al[r][3] = smA_lo[base + 8 * PSTRIDE + 4];
            }
#pragma unroll
            for (int c = 0; c < 4; ++c) {
                int nt = w * 4 + c;
                uint2 bh = __ldg(&g_Bhi[(s * 16 + nt) * 32 + lane]);
                uint2 bl = __ldg(&g_Blo[(s * 16 + nt) * 32 + lane]);
#pragma unroll
                for (int r = 0; r < 3; ++r) {
                    MMA_BF16(acc[r][c], ah[r], bh.x, bh.y);
                    MMA_BF16(acc[r][c], al[r], bh.x, bh.y);
                    MMA_BF16(acc[r][c], ah[r], bl.x, bl.y);
                }
            }
        }

        // epilogue: d0,d1 -> (row 16r+g, cols 2t,2t+1); d2,d3 -> row +8
#pragma unroll
        for (int r = 0; r < 3; ++r) {
            const long long rowA = (long long)(row0 + 16 * r + g);
            const long long rowB = rowA + 8;
            const bool vA = rowA < NROWS;
            const bool vB = rowB < NROWS;
#pragma unroll
            for (int c = 0; c < 4; ++c) {
                const int col = 32 * w + 8 * c + 2 * t;
                if (vA) {
                    float2 v0 = make_float2(acc[r][c][0], acc[r][c][1]);
                    *reinterpret_cast<float2*>(out + rowA * OUT_F + col) = v0;
                }
                if (vB) {
                    float2 v1 = make_float2(acc[r][c][2], acc[r][c][3]);
                    *reinterpret_cast<float2*>(out + rowB * OUT_F + col) = v1;
                }
            }
        }
    }
}

// ---------------------------------------------------------------------------
extern "C" void kernel_launch(void* const* d_in, const int* in_sizes, int n_in,
                              void* d_out, int out_size) {
    const float* T  = (const float*)d_in[0];
    const float* O1 = (const float*)d_in[1];
    const float* O2 = (const float*)d_in[2];
    const float* W  = (const float*)d_in[3];
    const float* s  = (const float*)d_in[4];
    float* out = (float*)d_out;

    cudaFuncSetAttribute(fused_attention_kernel,
                         cudaFuncAttributeMaxDynamicSharedMemorySize, SMEM_BYTES);

    compute_u_kernel<<<32, 256>>>(W, s);
    pack_b_kernel<<<dim3(16, 16), 32>>>(W);
    fused_attention_kernel<<<NBLK, THREADS, SMEM_BYTES>>>(T, O1, O2, out);
}